// round 5
// baseline (speedup 1.0000x reference)
#include <cuda_runtime.h>

// SMFNet B=2,N=8192,D=64,DV=64,M=3 — chord mask = diag + superdiag(wrap).
// Per iter: V'[i] = a_i V[i] + c_i V[i+1].  Unrolled over M=3:
//   V3[i] = (w0 X[i] + w1 X[i+1] + w2 X[i+2] + w3 X[i+3]) @ Wg + (sum w)*bg
// Single fused kernel; Wf tile staged to smem with coalesced loads.

#define Bc   2
#define Nc   8192
#define Dc   64
#define TROWS 32          // output rows per CTA -> 512 CTAs
#define XROWS 35          // X rows staged (TROWS+3)
#define XPAD  68          // float4-aligned stride (272B)
#define WFC   35          // Wf columns staged (r0 .. r0+34)
#define WFP   36          // Wf tile col stride
#define XWPAD 65          // conflict-free scalar stride
#define ACR   36
#define NTHREADS 256

// smem layout (floats)
#define OFF_XS    0                          // XROWS*XPAD        = 2380
#define OFF_WFS   (OFF_XS  + XROWS*XPAD)     // 3*64*WFP          = 6912
#define OFF_XWS   (OFF_WFS + 3*64*WFP)       // TROWS*XWPAD       = 2080
#define OFF_AS    (OFF_XWS + TROWS*XWPAD)    // 3*ACR
#define OFF_CS    (OFF_AS  + 3*ACR)          // 3*ACR
#define OFF_WC    (OFF_CS  + 3*ACR)          // TROWS*4
#define OFF_WSUM  (OFF_WC  + TROWS*4)        // TROWS
#define SMEM_FLOATS (OFF_WSUM + TROWS)
#define SMEM_BYTES  (SMEM_FLOATS * 4)

__device__ __forceinline__ unsigned long long pack2(float x, float y) {
    unsigned long long r;
    asm("mov.b64 %0, {%1, %2};" : "=l"(r) : "f"(x), "f"(y));
    return r;
}
__device__ __forceinline__ void unpack2(unsigned long long v, float& x, float& y) {
    asm("mov.b64 {%0, %1}, %2;" : "=f"(x), "=f"(y) : "l"(v));
}
__device__ __forceinline__ void fma2(unsigned long long& d,
                                     unsigned long long a, unsigned long long b) {
    asm("fma.rn.f32x2 %0, %1, %2, %3;" : "=l"(d) : "l"(a), "l"(b), "l"(d));
}

__global__ __launch_bounds__(NTHREADS, 4)
void smf_fused_kernel(const float* __restrict__ X,
                      const float* __restrict__ Wg,
                      const float* __restrict__ bg,
                      const float* __restrict__ Wf,
                      const float* __restrict__ bf,
                      float* __restrict__ out)
{
    extern __shared__ float sm[];
    float* Xs   = sm + OFF_XS;
    float* Wfs  = sm + OFF_WFS;
    float* Xws  = sm + OFF_XWS;
    float* As   = sm + OFF_AS;
    float* Cs   = sm + OFF_CS;
    float* Wc   = sm + OFF_WC;
    float* Wsum = sm + OFF_WSUM;

    const int t  = threadIdx.x;
    const int b  = blockIdx.y;
    const int r0 = blockIdx.x * TROWS;
    const float* Xb = X + (size_t)b * Nc * Dc;

    // ---- Phase 1: stage X rows (float4) + Wf tile (coalesced scalar) ----
    {
        const float4* Xb4 = reinterpret_cast<const float4*>(Xb);
        #pragma unroll
        for (int idx = t; idx < XROWS * 16; idx += NTHREADS) {
            int j = idx >> 4, q = idx & 15;
            int gi = (r0 + j) & (Nc - 1);
            *reinterpret_cast<float4*>(&Xs[j * XPAD + q * 4]) = Xb4[gi * 16 + q];
        }
        // Wf tile: rows (m,d) of WFC=35 contiguous columns starting at r0 (wrap).
        // 3*64*35 = 6720 elements.
        for (int idx = t; idx < 3 * 64 * WFC; idx += NTHREADS) {
            int row = idx / WFC;            // m*64 + d
            int c   = idx - row * WFC;      // 0..34
            int gi  = (r0 + c) & (Nc - 1);
            Wfs[row * WFP + c] = __ldg(Wf + (size_t)row * Nc + gi);
        }
    }
    __syncthreads();

    // ---- Phase 2: A/C dots from smem. 204 tasks: q=(m,isC), j=0..33 ----
    if (t < 6 * 34) {
        const int q = t / 34;
        const int j = t - q * 34;
        const int m   = q >> 1;
        const int isC = q & 1;
        const int col = j + isC;
        const int gi  = (r0 + col) & (Nc - 1);
        const float* wrow = &Wfs[(m * 64) * WFP + col];
        float acc = 0.f;
        #pragma unroll 16
        for (int d = 0; d < Dc; d++)
            acc = fmaf(Xs[j * XPAD + d], wrow[d * WFP], acc);
        acc += __ldg(bf + m * Nc + gi);
        (isC ? Cs : As)[m * ACR + j] = acc;
    }
    __syncthreads();

    // ---- Phase 3: 4-tap weights per output row ----
    if (t < TROWS) {
        const int j = t;
        float A1i  = As[0 * ACR + j], A1i1 = As[0 * ACR + j + 1], A1i2 = As[0 * ACR + j + 2];
        float C1i  = Cs[0 * ACR + j], C1i1 = Cs[0 * ACR + j + 1], C1i2 = Cs[0 * ACR + j + 2];
        float A2i  = As[1 * ACR + j], A2i1 = As[1 * ACR + j + 1];
        float C2i  = Cs[1 * ACR + j], C2i1 = Cs[1 * ACR + j + 1];
        float A3   = As[2 * ACR + j], C3   = Cs[2 * ACR + j];
        float w0 = A3 * A2i * A1i;
        float w1 = A3 * (A2i * C1i + C2i * A1i1) + C3 * A2i1 * A1i1;
        float w2 = A3 * C2i * C1i1 + C3 * (A2i1 * C1i1 + C2i1 * A1i2);
        float w3 = C3 * C2i1 * C1i2;
        Wc[j * 4 + 0] = w0; Wc[j * 4 + 1] = w1;
        Wc[j * 4 + 2] = w2; Wc[j * 4 + 3] = w3;
        Wsum[j] = w0 + w1 + w2 + w3;
    }
    __syncthreads();

    // ---- Phase 4: combined rows Xw[j] = sum_k w_k X[j+k] ----
    #pragma unroll
    for (int idx = t; idx < TROWS * 64; idx += NTHREADS) {
        int j = idx >> 6, d = idx & 63;
        float v = Wc[j * 4 + 0] * Xs[ j      * XPAD + d]
                + Wc[j * 4 + 1] * Xs[(j + 1) * XPAD + d]
                + Wc[j * 4 + 2] * Xs[(j + 2) * XPAD + d]
                + Wc[j * 4 + 3] * Xs[(j + 3) * XPAD + d];
        Xws[j * XWPAD + d] = v;
    }
    __syncthreads();

    // ---- Phase 5: matvec Xw @ Wg + wsum*bg (Wg via LDG/L1, f32x2 FMA) ----
    // thread tile: rows {rc, rc+16}, cols [e0, e0+4)
    {
        const int rc = t & 15;
        const int e0 = (t >> 4) * 4;
        unsigned long long acc00 = 0, acc01 = 0, acc10 = 0, acc11 = 0;

        #pragma unroll 8
        for (int d = 0; d < Dc; d++) {
            float4 wv = __ldg(reinterpret_cast<const float4*>(Wg + d * 64 + e0));
            unsigned long long w01 = pack2(wv.x, wv.y);
            unsigned long long w23 = pack2(wv.z, wv.w);
            float x0 = Xws[ rc       * XWPAD + d];
            float x1 = Xws[(rc + 16) * XWPAD + d];
            unsigned long long xx0 = pack2(x0, x0);
            unsigned long long xx1 = pack2(x1, x1);
            fma2(acc00, xx0, w01);
            fma2(acc01, xx0, w23);
            fma2(acc10, xx1, w01);
            fma2(acc11, xx1, w23);
        }

        float bgx = __ldg(bg + e0 + 0), bgy = __ldg(bg + e0 + 1);
        float bgz = __ldg(bg + e0 + 2), bgw = __ldg(bg + e0 + 3);

        float a0, a1, a2, a3;
        {
            const int j  = rc;
            const int gi = (r0 + j) & (Nc - 1);
            const float ws = Wsum[j];
            unpack2(acc00, a0, a1); unpack2(acc01, a2, a3);
            float4 o;
            o.x = a0 + ws * bgx;  o.y = a1 + ws * bgy;
            o.z = a2 + ws * bgz;  o.w = a3 + ws * bgw;
            *reinterpret_cast<float4*>(&out[((size_t)b * Nc + gi) * 64 + e0]) = o;
        }
        {
            const int j  = rc + 16;
            const int gi = (r0 + j) & (Nc - 1);
            const float ws = Wsum[j];
            unpack2(acc10, a0, a1); unpack2(acc11, a2, a3);
            float4 o;
            o.x = a0 + ws * bgx;  o.y = a1 + ws * bgy;
            o.z = a2 + ws * bgz;  o.w = a3 + ws * bgw;
            *reinterpret_cast<float4*>(&out[((size_t)b * Nc + gi) * 64 + e0]) = o;
        }
    }
}

extern "C" void kernel_launch(void* const* d_in, const int* in_sizes, int n_in,
                              void* d_out, int out_size)
{
    const float* X  = (const float*)d_in[0];   // (2, 8192, 64)
    const float* Wg = (const float*)d_in[1];   // (64, 64)
    const float* bg = (const float*)d_in[2];   // (64,)
    const float* Wf = (const float*)d_in[3];   // (3, 64, 8192)
    const float* bf = (const float*)d_in[4];   // (3, 8192)
    float* out = (float*)d_out;                // (2, 8192, 64)

    cudaFuncSetAttribute(smf_fused_kernel,
                         cudaFuncAttributeMaxDynamicSharedMemorySize, SMEM_BYTES);

    dim3 grid(Nc / TROWS, Bc);                 // (256, 2) = 512 CTAs
    smf_fused_kernel<<<grid, NTHREADS, SMEM_BYTES>>>(X, Wg, bg, Wf, bf, out);
}

// round 6
// speedup vs baseline: 1.1196x; 1.1196x over previous
#include <cuda_runtime.h>

// SMFNet B=2,N=8192,D=64,DV=64,M=3 — chord mask = diag + superdiag(wrap).
// out = S · V0 where V0 = X@Wg + bg and S is the 4-banded product of the
// three 2-banded chord matrices:
//   out[i] = w0 V0[i] + w1 V0[i+1] + w2 V0[i+2] + w3 V0[i+3]   (wrap)
//   w0 = A3 A2_i A1_i
//   w1 = A3 (A2_i C1_i + C2_i A1_{i+1}) + C3 A2_{i+1} A1_{i+1}
//   w2 = A3 C2_i C1_{i+1} + C3 (A2_{i+1} C1_{i+1} + C2_{i+1} A1_{i+2})
//   w3 = C3 C2_{i+1} C1_{i+2}
//   Am_j = X[j]·Wf[m][:,j] + bf[m][j],  Cm_j = X[j]·Wf[m][:,j+1] + bf[m][j+1]
// One fused kernel, 2 barriers, both batches per CTA, A/C ∥ GEMM in one phase.

#define Bc   2
#define Nc   8192
#define Dc   64
#define TROWS 16           // output rows per CTA  -> 512 CTAs
#define XR    19           // staged rows per batch (TROWS + 3 halo)
#define RS    (2*XR)       // row-slots (both batches) = 38
#define PAD   68           // float4-aligned row stride
#define ACW   20           // A/C stride per (b,m); j = 0..17 used
#define NTHREADS 256

// smem (floats)
#define OFF_XS  0                      // RS*PAD = 2584
#define OFF_VS  (OFF_XS + RS*PAD)      // RS*PAD = 2584  (byte 10336, 16B-aligned)
#define OFF_AS  (OFF_VS + RS*PAD)      // 6*ACW = 120
#define OFF_CS  (OFF_AS + 6*ACW)       // 120
#define SMEM_FLOATS (OFF_CS + 6*ACW)
#define SMEM_BYTES  (SMEM_FLOATS * 4)

__device__ __forceinline__ unsigned long long pack2(float x, float y) {
    unsigned long long r;
    asm("mov.b64 %0, {%1, %2};" : "=l"(r) : "f"(x), "f"(y));
    return r;
}
__device__ __forceinline__ void unpack2(unsigned long long v, float& x, float& y) {
    asm("mov.b64 {%0, %1}, %2;" : "=f"(x), "=f"(y) : "l"(v));
}
__device__ __forceinline__ void fma2(unsigned long long& d,
                                     unsigned long long a, unsigned long long b) {
    asm("fma.rn.f32x2 %0, %1, %2, %3;" : "=l"(d) : "l"(a), "l"(b), "l"(d));
}

__global__ __launch_bounds__(NTHREADS, 4)
void smf_fused_kernel(const float* __restrict__ X,
                      const float* __restrict__ Wg,
                      const float* __restrict__ bg,
                      const float* __restrict__ Wf,
                      const float* __restrict__ bf,
                      float* __restrict__ out)
{
    extern __shared__ float sm[];
    float* Xs = sm + OFF_XS;   // [RS][PAD]  rs = b*19 + j
    float* Vs = sm + OFF_VS;   // [RS][PAD]
    float* As = sm + OFF_AS;   // [(b*3+m)*ACW + j]
    float* Cs = sm + OFF_CS;

    const int t  = threadIdx.x;
    const int r0 = blockIdx.x * TROWS;

    // ---- Phase A: stage X rows r0..r0+18 (wrap) for both batches ----
    {
        const float4* X4 = reinterpret_cast<const float4*>(X);
        #pragma unroll
        for (int idx = t; idx < RS * 16; idx += NTHREADS) {
            int rs = idx >> 4, q = idx & 15;
            int b  = rs >= XR;
            int j  = rs - b * XR;
            int gi = (r0 + j) & (Nc - 1);
            *reinterpret_cast<float4*>(&Xs[rs * PAD + q * 4]) =
                X4[((size_t)b * Nc + gi) * 16 + q];
        }
    }
    __syncthreads();

    // ---- Phase B1: A/C dots (216 tasks), direct LDG, coalesced in j ----
    if (t < 216) {
        const int j = t % 18;
        const int g = t / 18;           // 0..11
        const int isC = g & 1;
        const int m   = (g >> 1) % 3;
        const int b   = g / 6;
        const int gic = (r0 + j + isC) & (Nc - 1);
        const float* wp = Wf + (size_t)m * Dc * Nc + gic;
        const float* xp = &Xs[(b * XR + j) * PAD];
        float acc = 0.f;
        #pragma unroll 16
        for (int d = 0; d < Dc; d++)
            acc = fmaf(xp[d], __ldg(wp + (size_t)d * Nc), acc);
        acc += __ldg(bf + m * Nc + gic);
        (isC ? Cs : As)[(b * 3 + m) * ACW + j] = acc;
    }

    // ---- Phase B2: GEMM V0 = X@Wg + bg for all 38 row-slots ----
    // thread: col quad e0 = 4*(t&15); row-slots rsb, rsb+16, (+32 if <38)
    {
        const int e0  = (t & 15) * 4;
        const int rsb = t >> 4;
        float4 bgq = __ldg(reinterpret_cast<const float4*>(bg + e0));
        unsigned long long a0_01 = pack2(bgq.x, bgq.y), a0_23 = pack2(bgq.z, bgq.w);
        unsigned long long a1_01 = a0_01, a1_23 = a0_23;
        unsigned long long a2_01 = a0_01, a2_23 = a0_23;
        const bool has3 = (rsb < RS - 32);     // rsb < 6 — uniform per warp

        #pragma unroll 8
        for (int d = 0; d < Dc; d++) {
            float4 wv = __ldg(reinterpret_cast<const float4*>(Wg + d * 64 + e0));
            unsigned long long w01 = pack2(wv.x, wv.y);
            unsigned long long w23 = pack2(wv.z, wv.w);
            float x0 = Xs[ rsb       * PAD + d];
            float x1 = Xs[(rsb + 16) * PAD + d];
            unsigned long long xx0 = pack2(x0, x0);
            unsigned long long xx1 = pack2(x1, x1);
            fma2(a0_01, xx0, w01);  fma2(a0_23, xx0, w23);
            fma2(a1_01, xx1, w01);  fma2(a1_23, xx1, w23);
            if (has3) {
                float x2 = Xs[(rsb + 32) * PAD + d];
                unsigned long long xx2 = pack2(x2, x2);
                fma2(a2_01, xx2, w01);  fma2(a2_23, xx2, w23);
            }
        }
        float v0, v1, v2, v3;
        unpack2(a0_01, v0, v1); unpack2(a0_23, v2, v3);
        float4* vdst = reinterpret_cast<float4*>(&Vs[rsb * PAD + e0]);
        *vdst = make_float4(v0, v1, v2, v3);
        unpack2(a1_01, v0, v1); unpack2(a1_23, v2, v3);
        vdst = reinterpret_cast<float4*>(&Vs[(rsb + 16) * PAD + e0]);
        *vdst = make_float4(v0, v1, v2, v3);
        if (has3) {
            unpack2(a2_01, v0, v1); unpack2(a2_23, v2, v3);
            vdst = reinterpret_cast<float4*>(&Vs[(rsb + 32) * PAD + e0]);
            *vdst = make_float4(v0, v1, v2, v3);
        }
    }
    __syncthreads();

    // ---- Phase C: weights (inline) + 4-tap combine + store ----
    // thread: quad e0, row jr = t>>4 (0..15), both batches
    {
        const int e0 = (t & 15) * 4;
        const int jr = t >> 4;
        #pragma unroll
        for (int b = 0; b < Bc; b++) {
            const float* A1 = &As[(b * 3 + 0) * ACW];
            const float* C1 = &Cs[(b * 3 + 0) * ACW];
            const float* A2 = &As[(b * 3 + 1) * ACW];
            const float* C2 = &Cs[(b * 3 + 1) * ACW];
            const float* A3p = &As[(b * 3 + 2) * ACW];
            const float* C3p = &Cs[(b * 3 + 2) * ACW];
            float A1i = A1[jr], A1i1 = A1[jr + 1], A1i2 = A1[jr + 2];
            float C1i = C1[jr], C1i1 = C1[jr + 1], C1i2 = C1[jr + 2];
            float A2i = A2[jr], A2i1 = A2[jr + 1];
            float C2i = C2[jr], C2i1 = C2[jr + 1];
            float A3  = A3p[jr], C3 = C3p[jr];
            float w0 = A3 * A2i * A1i;
            float w1 = A3 * (A2i * C1i + C2i * A1i1) + C3 * A2i1 * A1i1;
            float w2 = A3 * C2i * C1i1 + C3 * (A2i1 * C1i1 + C2i1 * A1i2);
            float w3 = C3 * C2i1 * C1i2;

            const float* vb = &Vs[(b * XR + jr) * PAD + e0];
            float4 p0 = *reinterpret_cast<const float4*>(vb);
            float4 p1 = *reinterpret_cast<const float4*>(vb + PAD);
            float4 p2 = *reinterpret_cast<const float4*>(vb + 2 * PAD);
            float4 p3 = *reinterpret_cast<const float4*>(vb + 3 * PAD);

            float4 o;
            o.x = w0 * p0.x + w1 * p1.x + w2 * p2.x + w3 * p3.x;
            o.y = w0 * p0.y + w1 * p1.y + w2 * p2.y + w3 * p3.y;
            o.z = w0 * p0.z + w1 * p1.z + w2 * p2.z + w3 * p3.z;
            o.w = w0 * p0.w + w1 * p1.w + w2 * p2.w + w3 * p3.w;

            const int gi = r0 + jr;    // r0+jr <= 8191, no wrap for outputs
            *reinterpret_cast<float4*>(&out[((size_t)b * Nc + gi) * 64 + e0]) = o;
        }
    }
}

extern "C" void kernel_launch(void* const* d_in, const int* in_sizes, int n_in,
                              void* d_out, int out_size)
{
    const float* X  = (const float*)d_in[0];   // (2, 8192, 64)
    const float* Wg = (const float*)d_in[1];   // (64, 64)
    const float* bg = (const float*)d_in[2];   // (64,)
    const float* Wf = (const float*)d_in[3];   // (3, 64, 8192)
    const float* bf = (const float*)d_in[4];   // (3, 8192)
    float* out = (float*)d_out;                // (2, 8192, 64)

    cudaFuncSetAttribute(smf_fused_kernel,
                         cudaFuncAttributeMaxDynamicSharedMemorySize, SMEM_BYTES);

    dim3 grid(Nc / TROWS, 1);                  // 512 CTAs, both batches per CTA
    smf_fused_kernel<<<grid, NTHREADS, SMEM_BYTES>>>(X, Wg, bg, Wf, bf, out);
}